// round 2
// baseline (speedup 1.0000x reference)
#include <cuda_runtime.h>

// 2x nearest-neighbor upsample:
// in:  float32 [16, 64, 256, 256]  (B*C = 1024 planes of 256x256)
// out: float32 [16, 64, 512, 512]
//
// Each thread: load one float4 (4 input pixels in a row), write 2 rows x 2
// float4 (each input pixel duplicated 2x horizontally, row duplicated 2x
// vertically). 16B load -> 64B stores per thread, fully coalesced.

#define H_IN   256
#define W_IN   256
#define W_IN4  (W_IN / 4)          // 64 float4 per input row
#define W_OUT  512
#define W_OUT4 (W_OUT / 4)         // 128 float4 per output row

__global__ void __launch_bounds__(256) upsample2x_kernel(
    const float4* __restrict__ in4, float4* __restrict__ out4, int total4)
{
    int idx = blockIdx.x * blockDim.x + threadIdx.x;
    if (idx >= total4) return;

    // idx -> (plane, h, wq)
    int wq    = idx & (W_IN4 - 1);          // 0..63
    int h     = (idx >> 6) & (H_IN - 1);    // 0..255
    int plane = idx >> 14;                  // 0..1023

    float4 v = in4[idx];

    float4 lo = make_float4(v.x, v.x, v.y, v.y);
    float4 hi = make_float4(v.z, v.z, v.w, v.w);

    // output row base (in float4 units) for row 2h of this plane
    long long rowbase = ((long long)plane * (2 * H_IN) + 2 * h) * W_OUT4 + 2 * wq;

    out4[rowbase]              = lo;
    out4[rowbase + 1]          = hi;
    out4[rowbase + W_OUT4]     = lo;
    out4[rowbase + W_OUT4 + 1] = hi;
}

extern "C" void kernel_launch(void* const* d_in, const int* in_sizes, int n_in,
                              void* d_out, int out_size)
{
    const float4* in4 = (const float4*)d_in[0];
    float4* out4 = (float4*)d_out;

    int total4 = in_sizes[0] / 4;           // 16*64*256*256/4 = 16,777,216
    int threads = 256;
    int blocks = (total4 + threads - 1) / threads;

    upsample2x_kernel<<<blocks, threads>>>(in4, out4, total4);
}

// round 4
// speedup vs baseline: 1.1243x; 1.1243x over previous
#include <cuda_runtime.h>

// 2x nearest-neighbor upsample:
// in:  float32 [16, 64, 256, 256]  (1024 planes of 256x256)
// out: float32 [16, 64, 512, 512]
//
// Thread indexing over OUTPUT quads so every STG.128 is lane-contiguous:
//   thread idx -> (plane, h_in, ow4) with ow4 = output-quad column (0..127)
//   input needed: float2 at (plane, h_in, 2 cols)  -> in2[idx]  (same linear index!)
//   output: quad (x,x,y,y) stored to rows 2h and 2h+1 at column ow4.
// Per warp: 1 x LDG.64 (256B contiguous) + 2 x STG.128 (512B contiguous each).
// Store wavefronts at the 128B-sector floor; input read exactly once.

#define W_OUT4 128                  // float4 per output row (512/4)

__global__ void __launch_bounds__(256) upsample2x_outidx_kernel(
    const float2* __restrict__ in2, float4* __restrict__ out4, int total)
{
    int idx = blockIdx.x * blockDim.x + threadIdx.x;
    if (idx >= total) return;

    // idx -> (plane, h, ow4); input float2 index == idx
    int ow4   = idx & (W_OUT4 - 1);         // 0..127
    int h     = (idx >> 7) & 255;           // 0..255
    int plane = idx >> 15;                  // 0..1023

    float2 v = in2[idx];
    float4 q = make_float4(v.x, v.x, v.y, v.y);

    // output row 2h of this plane, column ow4 (float4 units)
    long long base = ((long long)plane * 512 + 2 * h) * W_OUT4 + ow4;

    out4[base]          = q;   // row 2h
    out4[base + W_OUT4] = q;   // row 2h+1
}

extern "C" void kernel_launch(void* const* d_in, const int* in_sizes, int n_in,
                              void* d_out, int out_size)
{
    const float2* in2 = (const float2*)d_in[0];
    float4* out4 = (float4*)d_out;

    int total = in_sizes[0] / 2;            // 16*64*256*256/2 = 33,554,432 threads
    int threads = 256;
    int blocks = (total + threads - 1) / threads;

    upsample2x_outidx_kernel<<<blocks, threads>>>(in2, out4, total);
}